// round 13
// baseline (speedup 1.0000x reference)
#include <cuda_runtime.h>
#include <cstdint>

#define NN 64
#define NMAT 4096
#define GPB 2                      // 128-thread groups per 256-thread block
#define THREADS 256
#define BLOCKS 456                 // 3 blocks/SM x 152 SMs
#define NGROUPS (BLOCKS * GPB)     // 912 independent pipelines
#define MATVECS 3                  // + rowsum = 4 applications total
#define RP 68                      // tile row pitch (words): conflict-free
#define TILEW (NN * RP)            // 4352 words per tile
#define SMEM_WORDS (GPB * (2 * TILEW + 2 * NN))
#define SMEM_BYTES (SMEM_WORDS * 4)   // 70656

__device__ float g_acc[NN];
__device__ unsigned int g_ticket;

typedef unsigned long long u64;

__device__ __forceinline__ u64 ffma2(u64 a, u64 b, u64 c) {
    u64 d;
    asm("fma.rn.f32x2 %0, %1, %2, %3;" : "=l"(d) : "l"(a), "l"(b), "l"(c));
    return d;
}
__device__ __forceinline__ u64 fadd2(u64 a, u64 b) {
    u64 d;
    asm("add.rn.f32x2 %0, %1, %2;" : "=l"(d) : "l"(a), "l"(b));
    return d;
}
__device__ __forceinline__ void cp16(uint32_t dst, const void* src) {
    asm volatile("cp.async.cg.shared.global [%0], [%1], 16;" :: "r"(dst), "l"(src));
}
__device__ __forceinline__ u64 pack(float lo, float hi) {
    float2 f = make_float2(lo, hi);
    return *reinterpret_cast<u64*>(&f);
}
#define GBAR() asm volatile("bar.sync %0, 128;" :: "r"(barid) : "memory")

// 128-thread fill of one 16KB tile via cp.async (no registers on the path).
// gmem coalesced; smem dst banks 4*((r+i2) mod 8): conflict-free.
__device__ __forceinline__ void issue_tile(float* bufp, const float* M, int l) {
    uint32_t b32 = (uint32_t)__cvta_generic_to_shared(bufp);
    const float4* src = reinterpret_cast<const float4*>(M);
#pragma unroll
    for (int j = 0; j < 8; ++j) {
        const int c = j * 128 + l;          // 16B-chunk 0..1023
        const int r = c >> 4, i2 = c & 15;
        cp16(b32 + (uint32_t)(r * RP + 4 * i2) * 4u, src + c);
    }
}

// 128 threads per matrix: warp-lane wl -> row k = w*16 + (wl&15), half
// h = wl>>4 (columns [32h,32h+32), 16 u64 regs). Dot = 16 FFMA2 + 1 shfl.
// v reads: per instr the two half-addresses are bank-disjoint via the
// (i+4h)&7 chunk rotation -> 1 wavefront each. Named barrier per group;
// cp.async double buffer carried across the persistent loop.
__global__ __launch_bounds__(THREADS, 3)
void power_kernel(const float* __restrict__ x,
                  const float* __restrict__ wt,
                  const float* __restrict__ rc,
                  float* __restrict__ out)
{
    extern __shared__ float smem[];
    const int t  = threadIdx.x;
    const int g  = t >> 7;               // group in block
    const int l  = t & 127;
    const int wl = l & 31;
    const int w  = l >> 5;               // warp in group
    const int h  = wl >> 4;              // half 0/1
    const int k  = w * 16 + (wl & 15);   // row 0..63
    const int barid = 1 + g;

    float* tile = smem + g * (2 * TILEW);
    float* vb   = smem + GPB * 2 * TILEW + g * (2 * NN);   // [2][64]

    const int g0 = (int)blockIdx.x * GPB + g;
    issue_tile(tile, rc + (size_t)g0 * NN * NN, l);
    asm volatile("cp.async.commit_group;" ::: "memory");
    if (g0 + NGROUPS < NMAT)
        issue_tile(tile + TILEW, rc + (size_t)(g0 + NGROUPS) * NN * NN, l);
    asm volatile("cp.async.commit_group;" ::: "memory");

#pragma unroll 1
    for (int i = 0, m = g0; m < NMAT; ++i, m += NGROUPS) {
        asm volatile("cp.async.wait_group 1;" ::: "memory");
        GBAR();                          // tile ready; prior vb reads done
        float* tl = tile + (i & 1) * TILEW;

        // Half-row -> regs: 8 conflict-free LDS.128.
        u64 row[16];
        {
            const float* bp = tl + k * RP + 32 * h;
#pragma unroll
            for (int j = 0; j < 8; ++j) {
                float4 f = *reinterpret_cast<const float4*>(bp + 4 * j);
                row[2 * j]     = pack(f.x, f.y);
                row[2 * j + 1] = pack(f.z, f.w);
            }
        }
        const int s = m >> 6;
        const float mss = tl[s * RP + s];            // broadcast (pre-prefetch)
        const float xw  = __ldg(x + m) * __ldg(wt + m);

        // App 0: v0 = M*ones = rowsum (v scale irrelevant: output = v[n]/v[s]).
        float vk;
        {
            u64 a0 = fadd2(row[0], row[4]),  a1 = fadd2(row[1], row[5]);
            u64 a2 = fadd2(row[2], row[6]),  a3 = fadd2(row[3], row[7]);
            a0 = fadd2(a0, fadd2(row[8],  row[12]));
            a1 = fadd2(a1, fadd2(row[9],  row[13]));
            a2 = fadd2(a2, fadd2(row[10], row[14]));
            a3 = fadd2(a3, fadd2(row[11], row[15]));
            u64 ss = fadd2(fadd2(a0, a2), fadd2(a1, a3));
            float2 f = *reinterpret_cast<float2*>(&ss);
            float p = f.x + f.y;
            p += __shfl_xor_sync(0xffffffffu, p, 16);   // combine halves
            vk = p;
            if (h == 0) vb[k] = p;                      // buffer 0
        }
        GBAR();                          // tile consumed + vb0 visible

        // Prefetch matrix m+2*NGROUPS into the freed tile (or empty group).
        if (m + 2 * NGROUPS < NMAT)
            issue_tile(tl, rc + (size_t)(m + 2 * NGROUPS) * NN * NN, l);
        asm volatile("cp.async.commit_group;" ::: "memory");

#pragma unroll
        for (int it = 0; it < MATVECS; ++it) {
            const float* vp = vb + (it & 1) * NN + 32 * h;
            u64 a0 = 0, a1 = 0, a2 = 0, a3 = 0;
#pragma unroll
            for (int i2 = 0; i2 < 8; ++i2) {
                const int idx = (i2 + 4 * h) & 7;   // bank-disjoint halves
                float4 f = *reinterpret_cast<const float4*>(vp + 4 * idx);
                if (i2 & 1) { a2 = ffma2(row[2 * idx],     pack(f.x, f.y), a2);
                              a3 = ffma2(row[2 * idx + 1], pack(f.z, f.w), a3); }
                else        { a0 = ffma2(row[2 * idx],     pack(f.x, f.y), a0);
                              a1 = ffma2(row[2 * idx + 1], pack(f.z, f.w), a1); }
            }
            u64 ss = fadd2(fadd2(a0, a2), fadd2(a1, a3));
            float2 f = *reinterpret_cast<float2*>(&ss);
            float p = f.x + f.y;
            p += __shfl_xor_sync(0xffffffffu, p, 16);
            vk = p;
            if (h == 0) vb[((it & 1) ^ 1) * NN + k] = p;  // it=2 -> buffer 1
            GBAR();
        }

        // Final v in buffer 1. h==0 lanes emit the 64 atomics.
        const float vs = vb[NN + s];
        if (h == 0)
            atomicAdd(&g_acc[k], xw * mss / vs * vk);
    }

    // Drain: last block copies g_acc -> out and resets scratch.
    __threadfence();
    __syncthreads();
    __shared__ int is_last;
    if (t == 0)
        is_last = (atomicAdd(&g_ticket, 1u) == (unsigned)(BLOCKS - 1));
    __syncthreads();
    if (is_last) {
        if (t < NN) { out[t] = g_acc[t]; g_acc[t] = 0.0f; }
        if (t == 0) g_ticket = 0u;
    }
}

extern "C" void kernel_launch(void* const* d_in, const int* in_sizes, int n_in,
                              void* d_out, int out_size)
{
    // inputs: x, weights_t, weights_r (unused), r_zeros (all-zero), r_const
    const float* x  = (const float*)d_in[0];
    const float* wt = (const float*)d_in[1];
    const float* rc = (const float*)d_in[4];

    static bool attr_set = false;
    if (!attr_set) {
        cudaFuncSetAttribute(power_kernel,
                             cudaFuncAttributeMaxDynamicSharedMemorySize,
                             SMEM_BYTES);
        cudaFuncSetAttribute(power_kernel,
                             cudaFuncAttributePreferredSharedMemoryCarveout, 100);
        attr_set = true;
    }
    power_kernel<<<BLOCKS, THREADS, SMEM_BYTES>>>(x, wt, rc, (float*)d_out);
}

// round 14
// speedup vs baseline: 1.0401x; 1.0401x over previous
#include <cuda_runtime.h>
#include <cstdint>

#define NN 64
#define NMAT 4096
#define GRID_P 760             // 5 blocks x 152 SMs: one resident wave
#define VAPPS 2                // + folded rowsum = 3 applications total
#define RP 68                  // tile row pitch (words): conflict-free
#define TILEW (NN * RP)        // 4352 words

__device__ float g_acc[NN];
__device__ unsigned int g_ticket;

typedef unsigned long long u64;

__device__ __forceinline__ u64 ffma2(u64 a, u64 b, u64 c) {
    u64 d;
    asm("fma.rn.f32x2 %0, %1, %2, %3;" : "=l"(d) : "l"(a), "l"(b), "l"(c));
    return d;
}
__device__ __forceinline__ u64 fadd2(u64 a, u64 b) {
    u64 d;
    asm("add.rn.f32x2 %0, %1, %2;" : "=l"(d) : "l"(a), "l"(b));
    return d;
}
__device__ __forceinline__ void cp16(uint32_t dst, const void* src) {
    asm volatile("cp.async.cg.shared.global [%0], [%1], 16;" :: "r"(dst), "l"(src));
}
__device__ __forceinline__ u64 pack(float lo, float hi) {
    float2 f = make_float2(lo, hi);
    return *reinterpret_cast<u64*>(&f);
}

// 256-thread fill of one 16KB tile: gmem coalesced (4 wf/instr, the floor),
// smem dst banks 4*((r+j) mod 8): conflict-free.  [validated R9/R10]
__device__ __forceinline__ void issue_tile(float* bufp, const float* M, int t) {
    uint32_t b32 = (uint32_t)__cvta_generic_to_shared(bufp);
    const float4* src = reinterpret_cast<const float4*>(M);
#pragma unroll
    for (int i = 0; i < 4; ++i) {
        const int c = i * 256 + t;
        const int r = c >> 4, j = c & 15;
        cp16(b32 + (uint32_t)(r * RP + 4 * j) * 4u, src + c);
    }
}

// Thread t -> (row k = t>>2, quarter q = t&3): quarter-row in 8 u64 regs.
// Matvec = 4 broadcast-group LDS.128 from staggered v copies (bank-disjoint
// q segments, validated R6) + 8 FFMA2 + shfl_xor(1,2) + 1 STS + ONE barrier.
// Fill via cp.async double buffer carried across the persistent loop.
__global__ __launch_bounds__(256, 5)
void power_kernel(const float* __restrict__ x,
                  const float* __restrict__ wt,
                  const float* __restrict__ rc,
                  float* __restrict__ out)
{
    const int t = threadIdx.x;
    const int k = t >> 2;       // row 0..63
    const int q = t & 3;        // quarter 0..3

    __shared__ __align__(16) float buf[2][TILEW];
    __shared__ __align__(16) float v[2][4][RP];   // staggered copies, dbl-buf
    __shared__ int is_last;

    const int m0 = (int)blockIdx.x;
    issue_tile(buf[0], rc + (size_t)m0 * NN * NN, t);
    asm volatile("cp.async.commit_group;" ::: "memory");
    if (m0 + GRID_P < NMAT)
        issue_tile(buf[1], rc + (size_t)(m0 + GRID_P) * NN * NN, t);
    asm volatile("cp.async.commit_group;" ::: "memory");

#pragma unroll 1
    for (int i = 0, m = m0; m < NMAT; ++i, m += GRID_P) {
        const int s = m >> 6;
        asm volatile("cp.async.wait_group 1;" ::: "memory");
        __syncthreads();            // tile ready; prior epilogue v-reads done
        const float* tl = buf[i & 1];

        const float xw  = __ldg(x + m) * __ldg(wt + m);
        const float mss = tl[s * RP + s];    // broadcast; pre-prefetch read

        // Quarter-row -> regs: 4 LDS.128 (4-way across q = the 128B/wf floor).
        u64 row[8];
        {
            const float* bp = tl + k * RP + 16 * q;
#pragma unroll
            for (int j = 0; j < 4; ++j) {
                float4 f = *reinterpret_cast<const float4*>(bp + 4 * j);
                row[2 * j]     = pack(f.x, f.y);
                row[2 * j + 1] = pack(f.z, f.w);
            }
        }

        // App 0: v0 = M*ones = rowsum, folded into registers (v scale is
        // irrelevant: the output uses v[n]/v[s]).
        float vk;
        {
            u64 s0 = fadd2(fadd2(row[0], row[1]), fadd2(row[2], row[3]));
            u64 s1 = fadd2(fadd2(row[4], row[5]), fadd2(row[6], row[7]));
            u64 ss = fadd2(s0, s1);
            float2 f = *reinterpret_cast<float2*>(&ss);
            float p = f.x + f.y;
            p += __shfl_xor_sync(0xffffffffu, p, 1);   // quarter partners are
            p += __shfl_xor_sync(0xffffffffu, p, 2);   // adjacent lanes
            vk = p;
            v[0][q][k] = p;        // each lane fills its own staggered copy
        }
        __syncthreads();            // tile consumed by all + v[0] visible

        // Prefetch matrix m+2*GRID_P into the freed buffer (or empty group).
        if (m + 2 * GRID_P < NMAT)
            issue_tile(buf[i & 1], rc + (size_t)(m + 2 * GRID_P) * NN * NN, t);
        asm volatile("cp.async.commit_group;" ::: "memory");

#pragma unroll
        for (int it = 0; it < VAPPS; ++it) {
            // Staggered copy q, segment [16q,16q+16): banks {4j,4j+20,4j+8,
            // 4j+28} across q -> conflict-free broadcast groups. [R6]
            const ulonglong2* vp =
                reinterpret_cast<const ulonglong2*>(&v[it & 1][q][16 * q]);
            ulonglong2 v0 = vp[0], v1 = vp[1], v2 = vp[2], v3 = vp[3];
            u64 a0 = ffma2(row[0], v0.x, 0ull);
            u64 a1 = ffma2(row[1], v0.y, 0ull);
            u64 a2 = ffma2(row[2], v1.x, 0ull);
            u64 a3 = ffma2(row[3], v1.y, 0ull);
            a0 = ffma2(row[4], v2.x, a0);
            a1 = ffma2(row[5], v2.y, a1);
            a2 = ffma2(row[6], v3.x, a2);
            a3 = ffma2(row[7], v3.y, a3);
            u64 ss = fadd2(fadd2(a0, a2), fadd2(a1, a3));
            float2 f = *reinterpret_cast<float2*>(&ss);
            float p = f.x + f.y;
            p += __shfl_xor_sync(0xffffffffu, p, 1);
            p += __shfl_xor_sync(0xffffffffu, p, 2);
            vk = p;
            v[(it & 1) ^ 1][q][k] = p;   // it=1 writes v[0] (final buffer)
            __syncthreads();             // ONE barrier per matvec
        }

        // Final v in v[0]; vk = v[k] (all 4 q-lanes hold it post-shfl).
        const float vs = v[0][0][s];
        if (q == 0)
            atomicAdd(&g_acc[k], xw * mss / vs * vk);
        // next iteration's top barrier orders these v-reads vs. new writes
    }

    // Last block drains g_acc -> out and resets scratch (graph-replay safe).
    __threadfence();
    if (t == 0)
        is_last = (atomicAdd(&g_ticket, 1u) == (unsigned)(GRID_P - 1));
    __syncthreads();
    if (is_last) {
        if (t < NN) { out[t] = g_acc[t]; g_acc[t] = 0.0f; }
        if (t == 0) g_ticket = 0u;
    }
}

extern "C" void kernel_launch(void* const* d_in, const int* in_sizes, int n_in,
                              void* d_out, int out_size)
{
    // inputs: x, weights_t, weights_r (unused), r_zeros (all-zero), r_const
    const float* x  = (const float*)d_in[0];
    const float* wt = (const float*)d_in[1];
    const float* rc = (const float*)d_in[4];

    static bool attr_set = false;
    if (!attr_set) {
        cudaFuncSetAttribute(power_kernel,
                             cudaFuncAttributePreferredSharedMemoryCarveout, 100);
        attr_set = true;
    }
    power_kernel<<<GRID_P, 256>>>(x, wt, rc, (float*)d_out);
}